// round 9
// baseline (speedup 1.0000x reference)
#include <cuda_runtime.h>
#include <cuda_pipeline.h>

// db4 dec_lo coefficients
static constexpr float Gf[8] = {
    -0.010597401784997278f,  0.032883011666982945f,
     0.030841381835986965f, -0.18703481171888114f,
    -0.02798376941698385f,   0.6308807679295904f,
     0.7148465705525415f,    0.23037781330885523f };

// Composed analysis+synthesis filters (details zeroed):
//   low[2q]   = sum_{d=-6..7} Ecoef(d) * x_sym[2q+d]
//   low[2q+1] = sum_{d=-6..7} Ocoef(d) * x_sym[2q+d]
__host__ __device__ static constexpr float Ecoef(int d) {
    float r = 0.f;
    for (int j = 0; j < 4; j++) {
        int s = 2 * j + 1 - d;
        if (s >= 0 && s < 8) r += Gf[2 * j + 1] * Gf[s];
    }
    return r;
}
__host__ __device__ static constexpr float Ocoef(int d) {
    float r = 0.f;
    for (int j = 0; j < 4; j++) {
        int s = 2 * j + 1 - d;
        if (s >= 0 && s < 8) r += Gf[2 * j] * Gf[s];
    }
    return r;
}

#define ROW_L   4096
#define SX_LEN  4112     // sx[m] = x_sym[m-8], m in [0,4112)

// Issue async copy of one full row (+ symmetric halos) into an smem buffer.
__device__ __forceinline__ void issue_row_copy(float* sxb, const float* xr, int t)
{
    float4* d4 = (float4*)sxb;
    const float4* x4 = (const float4*)xr;
#pragma unroll
    for (int ii = 0; ii < 4; ii++) {
        __pipeline_memcpy_async(&d4[t + ii * 256 + 2], &x4[t + ii * 256], 16);
    }
    if (t < 8) {
        __pipeline_memcpy_async(&sxb[t], &xr[7 - t], 4);          // left sym ext
    } else if (t < 16) {
        __pipeline_memcpy_async(&sxb[4096 + t], &xr[4103 - t], 4); // right sym ext
    }
}

__global__ __launch_bounds__(256, 6) void db4_persistent_kernel(
    const float* __restrict__ x,
    float* __restrict__ low,
    float* __restrict__ high,
    int rows)
{
    __shared__ float sx[2][SX_LEN];   // 32.9 KB double buffer

    const int t = threadIdx.x;
    int row = blockIdx.x;
    if (row >= rows) return;

    constexpr float E[14] = {
        Ecoef(-6), Ecoef(-5), Ecoef(-4), Ecoef(-3), Ecoef(-2), Ecoef(-1),
        Ecoef(0),  Ecoef(1),  Ecoef(2),  Ecoef(3),  Ecoef(4),  Ecoef(5),
        Ecoef(6),  Ecoef(7) };
    constexpr float O[14] = {
        Ocoef(-6), Ocoef(-5), Ocoef(-4), Ocoef(-3), Ocoef(-2), Ocoef(-1),
        Ocoef(0),  Ocoef(1),  Ocoef(2),  Ocoef(3),  Ocoef(4),  Ocoef(5),
        Ocoef(6),  Ocoef(7) };

    int buf = 0;
    // Preload first row into buffer 0
    issue_row_copy(sx[0], x + (size_t)row * ROW_L, t);
    __pipeline_commit();

    while (true) {
        const int nrow = row + gridDim.x;
        const bool have_next = (nrow < rows);
        if (have_next) {
            issue_row_copy(sx[buf ^ 1], x + (size_t)nrow * ROW_L, t);
            __pipeline_commit();
        }
        // Wait for current row's copy (leave next row's group in flight)
        if (have_next) __pipeline_wait_prior(1);
        else           __pipeline_wait_prior(0);
        __syncthreads();   // current buffer fully populated across threads

        const float4* s4 = (const float4*)sx[buf];
        float* __restrict__ lo = low + (size_t)row * ROW_L;
        float* __restrict__ hi = high + (size_t)row * ROW_L;

#pragma unroll
        for (int ii = 0; ii < 4; ii++) {
            const int i = t + ii * 256;    // float4 output idx; outputs n=4i..4i+3

            // window w[c] = sx[4i + c], c = 0..19 : 5 conflict-free float4 LDS
            float4 v0 = s4[i];
            float4 v1 = s4[i + 1];
            float4 v2 = s4[i + 2];
            float4 v3 = s4[i + 3];
            float4 v4 = s4[i + 4];
            float w[20];
            w[0]=v0.x;  w[1]=v0.y;  w[2]=v0.z;  w[3]=v0.w;
            w[4]=v1.x;  w[5]=v1.y;  w[6]=v1.z;  w[7]=v1.w;
            w[8]=v2.x;  w[9]=v2.y;  w[10]=v2.z; w[11]=v2.w;
            w[12]=v3.x; w[13]=v3.y; w[14]=v3.z; w[15]=v3.w;
            w[16]=v4.x; w[17]=v4.y; w[18]=v4.z; w[19]=v4.w;

            float l0 = 0.f, l1 = 0.f, l2 = 0.f, l3 = 0.f;
#pragma unroll
            for (int d = 0; d < 14; d++) {
                l0 += E[d] * w[d + 2];
                l1 += O[d] * w[d + 2];
                l2 += E[d] * w[d + 4];
                l3 += O[d] * w[d + 4];
            }

            __stcs(&((float4*)lo)[i], make_float4(l0, l1, l2, l3));
            __stcs(&((float4*)hi)[i], make_float4(v2.x - l0, v2.y - l1,
                                                  v2.z - l2, v2.w - l3));
        }

        if (!have_next) break;
        __syncthreads();   // all reads of 'buf' done before it is refilled next iter
        row = nrow;
        buf ^= 1;
    }
}

extern "C" void kernel_launch(void* const* d_in, const int* in_sizes, int n_in,
                              void* d_out, int out_size)
{
    const float* x = (const float*)d_in[0];
    const int n = in_sizes[0];              // B*C*L
    const int rows = n / ROW_L;             // 8192
    float* low = (float*)d_out;             // tuple order: (low_freq, high_freq)
    float* high = (float*)d_out + (size_t)n;

    int grid = 148 * 6;                     // persistent: ~6 CTAs/SM, single wave
    if (grid > rows) grid = rows;
    db4_persistent_kernel<<<grid, 256>>>(x, low, high, rows);
}

// round 10
// speedup vs baseline: 1.1173x; 1.1173x over previous
#include <cuda_runtime.h>

// db4 dec_lo coefficients
static constexpr float Gf[8] = {
    -0.010597401784997278f,  0.032883011666982945f,
     0.030841381835986965f, -0.18703481171888114f,
    -0.02798376941698385f,   0.6308807679295904f,
     0.7148465705525415f,    0.23037781330885523f };

// Composed analysis+synthesis filters (details zeroed):
//   low[2q]   = sum_{d=-6..7} Ecoef(d) * x_sym[2q+d]
//   low[2q+1] = sum_{d=-6..7} Ocoef(d) * x_sym[2q+d]
__host__ __device__ static constexpr float Ecoef(int d) {
    float r = 0.f;
    for (int j = 0; j < 4; j++) {
        int s = 2 * j + 1 - d;
        if (s >= 0 && s < 8) r += Gf[2 * j + 1] * Gf[s];
    }
    return r;
}
__host__ __device__ static constexpr float Ocoef(int d) {
    float r = 0.f;
    for (int j = 0; j < 4; j++) {
        int s = 2 * j + 1 - d;
        if (s >= 0 && s < 8) r += Gf[2 * j] * Gf[s];
    }
    return r;
}

#define ROW_L   4096
#define SEG_F   512          // floats of output per warp
#define TILE_F4 132          // (512 + 16) / 4 float4 per warp tile

// Each warp owns a private tile: tile[m] = x_sym[base + m - 8], m in [0, 528).
// No block-wide barrier anywhere; warps run fully autonomously.
__global__ __launch_bounds__(256) void db4_warp_kernel(
    const float* __restrict__ x,
    float* __restrict__ low,
    float* __restrict__ high)
{
    __shared__ float sx[8][TILE_F4 * 4];   // 8 warps x 528 floats = 16.9 KB

    const int t = threadIdx.x;
    const int w = t >> 5;
    const int l = t & 31;
    const size_t row = blockIdx.x;
    const float* __restrict__ xr = x + row * (size_t)ROW_L;

    const int base = w * SEG_F;            // this warp's output segment start
    float* tile = sx[w];
    float4* t4 = (float4*)tile;

    // --- load tile: 132 float4 by 32 lanes; lanes 0..3 take the 5th ---
#pragma unroll
    for (int jj = 0; jj < 5; jj++) {
        const int j = l + 32 * jj;
        if (jj == 4 && l >= TILE_F4 - 128) break;   // only j = 128..131
        const int g = base - 8 + 4 * j;             // global float index (mult of 4)
        if (g >= 0 && g + 3 < ROW_L) {
            t4[j] = __ldcs((const float4*)(xr + g));
        } else {
            // symmetric reflection: i<0 -> x[-1-i]; i>=L -> x[2L-1-i]
            float v[4];
#pragma unroll
            for (int r = 0; r < 4; r++) {
                int idx = g + r;
                idx = (idx < 0) ? (-1 - idx) : ((idx >= ROW_L) ? (2 * ROW_L - 1 - idx) : idx);
                v[r] = xr[idx];
            }
            t4[j] = make_float4(v[0], v[1], v[2], v[3]);
        }
    }
    __syncwarp();

    constexpr float E[14] = {
        Ecoef(-6), Ecoef(-5), Ecoef(-4), Ecoef(-3), Ecoef(-2), Ecoef(-1),
        Ecoef(0),  Ecoef(1),  Ecoef(2),  Ecoef(3),  Ecoef(4),  Ecoef(5),
        Ecoef(6),  Ecoef(7) };
    constexpr float O[14] = {
        Ocoef(-6), Ocoef(-5), Ocoef(-4), Ocoef(-3), Ocoef(-2), Ocoef(-1),
        Ocoef(0),  Ocoef(1),  Ocoef(2),  Ocoef(3),  Ocoef(4),  Ocoef(5),
        Ocoef(6),  Ocoef(7) };

    float* __restrict__ lo = low + row * (size_t)ROW_L;
    float* __restrict__ hi = high + row * (size_t)ROW_L;

#pragma unroll
    for (int ii = 0; ii < 4; ii++) {
        const int k4 = l + 32 * ii;            // tile float4 index of window start
        const int i_out = w * 128 + k4;        // global output float4 index

        // window w[c] = tile[4*k4 + c], c = 0..19 : 5 conflict-free float4 LDS
        float4 v0 = t4[k4];
        float4 v1 = t4[k4 + 1];
        float4 v2 = t4[k4 + 2];
        float4 v3 = t4[k4 + 3];
        float4 v4 = t4[k4 + 4];
        float wd[20];
        wd[0]=v0.x;  wd[1]=v0.y;  wd[2]=v0.z;  wd[3]=v0.w;
        wd[4]=v1.x;  wd[5]=v1.y;  wd[6]=v1.z;  wd[7]=v1.w;
        wd[8]=v2.x;  wd[9]=v2.y;  wd[10]=v2.z; wd[11]=v2.w;
        wd[12]=v3.x; wd[13]=v3.y; wd[14]=v3.z; wd[15]=v3.w;
        wd[16]=v4.x; wd[17]=v4.y; wd[18]=v4.z; wd[19]=v4.w;

        float l0 = 0.f, l1 = 0.f, l2 = 0.f, l3 = 0.f;
#pragma unroll
        for (int d = 0; d < 14; d++) {
            l0 += E[d] * wd[d + 2];
            l1 += O[d] * wd[d + 2];
            l2 += E[d] * wd[d + 4];
            l3 += O[d] * wd[d + 4];
        }

        ((float4*)lo)[i_out] = make_float4(l0, l1, l2, l3);
        ((float4*)hi)[i_out] = make_float4(v2.x - l0, v2.y - l1,
                                           v2.z - l2, v2.w - l3);
    }
}

extern "C" void kernel_launch(void* const* d_in, const int* in_sizes, int n_in,
                              void* d_out, int out_size)
{
    const float* x = (const float*)d_in[0];
    const int n = in_sizes[0];              // B*C*L
    const int rows = n / ROW_L;             // 8192
    float* low = (float*)d_out;             // tuple order: (low_freq, high_freq)
    float* high = (float*)d_out + (size_t)n;

    db4_warp_kernel<<<rows, 256>>>(x, low, high);
}

// round 11
// speedup vs baseline: 1.1249x; 1.0068x over previous
#include <cuda_runtime.h>

// db4 dec_lo coefficients
static constexpr float Gf[8] = {
    -0.010597401784997278f,  0.032883011666982945f,
     0.030841381835986965f, -0.18703481171888114f,
    -0.02798376941698385f,   0.6308807679295904f,
     0.7148465705525415f,    0.23037781330885523f };

// Composed analysis+synthesis filters (details zeroed):
//   low[2q]   = sum_{d=-6..7} Ecoef(d) * x_sym[2q+d]
//   low[2q+1] = sum_{d=-6..7} Ocoef(d) * x_sym[2q+d]
__host__ __device__ static constexpr float Ecoef(int d) {
    float r = 0.f;
    for (int j = 0; j < 4; j++) {
        int s = 2 * j + 1 - d;
        if (s >= 0 && s < 8) r += Gf[2 * j + 1] * Gf[s];
    }
    return r;
}
__host__ __device__ static constexpr float Ocoef(int d) {
    float r = 0.f;
    for (int j = 0; j < 4; j++) {
        int s = 2 * j + 1 - d;
        if (s >= 0 && s < 8) r += Gf[2 * j] * Gf[s];
    }
    return r;
}

#define ROW_L  4096
#define ROW_F4 1024

// Direct-LDG version: no shared memory, no barriers. Each thread computes
// outputs n = 4i..4i+3 from 5 overlapping float4 loads; neighbor overlap is
// served by L1/L2 (each DRAM line still fetched once).
__global__ __launch_bounds__(256) void db4_direct_kernel(
    const float* __restrict__ x,
    float* __restrict__ low,
    float* __restrict__ high)
{
    const int t = threadIdx.x;
    const size_t row = blockIdx.x;
    const float* __restrict__ xr = x + row * (size_t)ROW_L;
    const float4* __restrict__ x4 = (const float4*)xr;

    constexpr float E[14] = {
        Ecoef(-6), Ecoef(-5), Ecoef(-4), Ecoef(-3), Ecoef(-2), Ecoef(-1),
        Ecoef(0),  Ecoef(1),  Ecoef(2),  Ecoef(3),  Ecoef(4),  Ecoef(5),
        Ecoef(6),  Ecoef(7) };
    constexpr float O[14] = {
        Ocoef(-6), Ocoef(-5), Ocoef(-4), Ocoef(-3), Ocoef(-2), Ocoef(-1),
        Ocoef(0),  Ocoef(1),  Ocoef(2),  Ocoef(3),  Ocoef(4),  Ocoef(5),
        Ocoef(6),  Ocoef(7) };

    float* __restrict__ lo = low + row * (size_t)ROW_L;
    float* __restrict__ hi = high + row * (size_t)ROW_L;

#pragma unroll
    for (int ii = 0; ii < 4; ii++) {
        const int i = t + ii * 256;    // row-local float4 index, 0..1023

        // window w[c] = x_sym[4i + c - 8], c = 0..19  -> float4s j = i-2 .. i+2
        float4 v[5];
#pragma unroll
        for (int b = 0; b < 5; b++) {
            const int j = i - 2 + b;
            if (j >= 0 && j < ROW_F4) {
                v[b] = __ldcs(&x4[j]);
            } else {
                // symmetric reflection per element: idx<0 -> -1-idx; idx>=L -> 2L-1-idx
                float s[4];
#pragma unroll
                for (int r = 0; r < 4; r++) {
                    int idx = 4 * j + r;
                    idx = (idx < 0) ? (-1 - idx)
                                    : ((idx >= ROW_L) ? (2 * ROW_L - 1 - idx) : idx);
                    s[r] = xr[idx];
                }
                v[b] = make_float4(s[0], s[1], s[2], s[3]);
            }
        }

        float wd[20];
#pragma unroll
        for (int b = 0; b < 5; b++) {
            wd[4 * b + 0] = v[b].x; wd[4 * b + 1] = v[b].y;
            wd[4 * b + 2] = v[b].z; wd[4 * b + 3] = v[b].w;
        }

        float l0 = 0.f, l1 = 0.f, l2 = 0.f, l3 = 0.f;
#pragma unroll
        for (int d = 0; d < 14; d++) {
            l0 += E[d] * wd[d + 2];
            l1 += O[d] * wd[d + 2];
            l2 += E[d] * wd[d + 4];
            l3 += O[d] * wd[d + 4];
        }

        __stcs(&((float4*)lo)[i], make_float4(l0, l1, l2, l3));
        __stcs(&((float4*)hi)[i], make_float4(wd[8] - l0, wd[9] - l1,
                                              wd[10] - l2, wd[11] - l3));
    }
}

extern "C" void kernel_launch(void* const* d_in, const int* in_sizes, int n_in,
                              void* d_out, int out_size)
{
    const float* x = (const float*)d_in[0];
    const int n = in_sizes[0];              // B*C*L
    const int rows = n / ROW_L;             // 8192
    float* low = (float*)d_out;             // tuple order: (low_freq, high_freq)
    float* high = (float*)d_out + (size_t)n;

    db4_direct_kernel<<<rows, 256>>>(x, low, high);
}